// round 14
// baseline (speedup 1.0000x reference)
#include <cuda_runtime.h>
#include <cuda_fp16.h>
#include <math.h>
#include <stdint.h>

#define BB 4
#define TT 4096
#define DD 1024
#define M_TOTAL (BB*TT)

// ------------------------- scratch (device globals) -------------------------
__device__ __half g_xhi[M_TOTAL*DD];
__device__ __half g_whi[4*DD*DD];
__device__ __half g_qhi[M_TOTAL*DD];
__device__ __half g_khi[M_TOTAL*DD];
__device__ __half g_vhi[M_TOTAL*DD];
__device__ __half g_rhi[M_TOTAL*DD];

// ------------------------- helpers ------------------------------------------
__device__ __forceinline__ uint32_t smem_to_u32(const void* p) {
    uint32_t a;
    asm("{ .reg .u64 t; cvta.to.shared.u64 t, %1; cvt.u32.u64 %0, t; }" : "=r"(a) : "l"(p));
    return a;
}
__device__ __forceinline__ void cp_async16(uint32_t saddr, const void* g) {
    asm volatile("cp.async.cg.shared.global [%0], [%1], 16;" :: "r"(saddr), "l"(g));
}
#define CP_COMMIT() asm volatile("cp.async.commit_group;" ::: "memory")
#define CP_WAIT2()  asm volatile("cp.async.wait_group 2;" ::: "memory")
#define CP_WAIT1()  asm volatile("cp.async.wait_group 1;" ::: "memory")
#define CP_WAIT0()  asm volatile("cp.async.wait_group 0;" ::: "memory")

__device__ __forceinline__ void ldsm_x4(uint32_t* r, uint32_t addr) {
    asm volatile("ldmatrix.sync.aligned.m8n8.x4.shared.b16 {%0,%1,%2,%3}, [%4];"
        : "=r"(r[0]), "=r"(r[1]), "=r"(r[2]), "=r"(r[3]) : "r"(addr));
}
__device__ __forceinline__ void ldsm_x4_t(uint32_t* r, uint32_t addr) {
    asm volatile("ldmatrix.sync.aligned.m8n8.x4.trans.shared.b16 {%0,%1,%2,%3}, [%4];"
        : "=r"(r[0]), "=r"(r[1]), "=r"(r[2]), "=r"(r[3]) : "r"(addr));
}
__device__ __forceinline__ void mma_f16(float* d, const uint32_t* a, const uint32_t* b) {
    asm volatile("mma.sync.aligned.m16n8k16.row.col.f32.f16.f16.f32 "
        "{%0,%1,%2,%3}, {%4,%5,%6,%7}, {%8,%9}, {%0,%1,%2,%3};"
        : "+f"(d[0]), "+f"(d[1]), "+f"(d[2]), "+f"(d[3])
        : "r"(a[0]), "r"(a[1]), "r"(a[2]), "r"(a[3]), "r"(b[0]), "r"(b[1]));
}
__device__ __forceinline__ uint32_t pack_f16(float a, float b) {
    __half2 h = __floats2half2_rn(a, b);
    return *(uint32_t*)&h;
}

// ------------------------- conversion kernels --------------------------------
__global__ __launch_bounds__(256) void conv_x(
    const float* __restrict__ src, __half* __restrict__ hi, int n4)
{
    int i = blockIdx.x * 256 + threadIdx.x;
    if (i >= n4) return;
    float4 v = ((const float4*)src)[i];
    __half2 H0; H0.x = __float2half_rn(v.x); H0.y = __float2half_rn(v.y);
    __half2 H1; H1.x = __float2half_rn(v.z); H1.y = __float2half_rn(v.w);
    ((__half2*)hi)[2*i]   = H0;
    ((__half2*)hi)[2*i+1] = H1;
}

__global__ __launch_bounds__(256) void conv_w4(
    const float* __restrict__ s0, const float* __restrict__ s1,
    const float* __restrict__ s2, const float* __restrict__ s3,
    __half* __restrict__ hi, int n4)
{
    int i = blockIdx.x * 256 + threadIdx.x;
    if (i >= n4) return;
    int z = blockIdx.y;
    const float* src = (z == 0) ? s0 : ((z == 1) ? s1 : ((z == 2) ? s2 : s3));
    __half* dst = hi + (size_t)z * DD * DD;
    float4 v = ((const float4*)src)[i];
    __half2 H0; H0.x = __float2half_rn(v.x); H0.y = __float2half_rn(v.y);
    __half2 H1; H1.x = __float2half_rn(v.z); H1.y = __float2half_rn(v.w);
    ((__half2*)dst)[2*i]   = H0;
    ((__half2*)dst)[2*i+1] = H1;
}

// ------------------------- HMMA GEMM (128x128, BK=64, 3-stage) ---------------
// 16 iterations, 1 barrier each (wait -> barrier -> prefetch -> compute).
// Pitch 144 B per 64-half row (conflict-free ldmatrix, proven as APITCH).
#define GPITCH 144
#define AHI_O 0
#define BHI_O 18432                 // 128 * 144
#define STAGEB 36864
#define GSMEM  (3*STAGEB)           // 110592; x2 CTAs = 221184 <= 227KB

__global__ __launch_bounds__(256, 2) void mma_gemm(
    const __half* __restrict__ Ahi, const __half* __restrict__ Whi,
    __half* __restrict__ H0, __half* __restrict__ H1, __half* __restrict__ H2,
    float* __restrict__ Cf, const float* __restrict__ scale_ptr, int mode)
{
    extern __shared__ char smc[];
    uint32_t sb = smem_to_u32(smc);
    int t = threadIdx.x, lane = t & 31, w = t >> 5;
    int wm = w & 3, wn = w >> 2;
    int m0 = blockIdx.x * 128, n0 = blockIdx.y * 128, z = blockIdx.z;

    const __half* Wh = Whi + (size_t)z * DD * DD;
    const __half* aH = Ahi + (size_t)m0 * DD;
    const __half* bH = Wh + (size_t)n0 * DD;

    float acc[2][8][4];
    #pragma unroll
    for (int i = 0; i < 2; i++)
        #pragma unroll
        for (int n = 0; n < 8; n++)
            #pragma unroll
            for (int j = 0; j < 4; j++) acc[i][n][j] = 0.f;

    int lrA = t >> 1, lhalf = t & 1;
    uint32_t soA = (uint32_t)(lrA * GPITCH + lhalf * 64);
    size_t goA = (size_t)lrA * DD + lhalf * 32;

    #define PREFETCH(c) do { \
        uint32_t base_ = sb + ((c) % 3) * STAGEB; \
        int k0_ = (c) * 64; \
        _Pragma("unroll") \
        for (int j_ = 0; j_ < 4; j_++) { \
            cp_async16(base_ + AHI_O + soA + j_ * 16, aH + goA + k0_ + j_ * 8); \
            cp_async16(base_ + BHI_O + soA + j_ * 16, bH + goA + k0_ + j_ * 8); \
        } \
    } while (0)

    PREFETCH(0); CP_COMMIT();
    PREFETCH(1); CP_COMMIT();

    for (int c = 0; c < 16; c++) {
        if (c < 15) { CP_WAIT1(); }
        else        { CP_WAIT0(); }
        __syncthreads();
        if (c + 2 < 16) { PREFETCH(c + 2); CP_COMMIT(); }

        uint32_t base = sb + (c % 3) * STAGEB;
        #pragma unroll
        for (int kk = 0; kk < 4; kk++) {
            uint32_t ah[2][4];
            #pragma unroll
            for (int i = 0; i < 2; i++) {
                uint32_t ro = (uint32_t)((wm * 32 + i * 16 + (lane & 15)) * GPITCH
                                         + kk * 32 + (lane >> 4) * 16);
                ldsm_x4(ah[i], base + AHI_O + ro);
            }
            uint32_t bh[8][2];
            #pragma unroll
            for (int p = 0; p < 4; p++) {
                int mid = lane >> 3;
                int nr = wn * 64 + p * 16 + ((mid & 2) << 2) + (lane & 7);
                uint32_t ro = (uint32_t)(nr * GPITCH + kk * 32 + (mid & 1) * 16);
                uint32_t r4[4];
                ldsm_x4(r4, base + BHI_O + ro);
                bh[2*p][0] = r4[0]; bh[2*p][1] = r4[1];
                bh[2*p+1][0] = r4[2]; bh[2*p+1][1] = r4[3];
            }
            #pragma unroll
            for (int i = 0; i < 2; i++)
                #pragma unroll
                for (int n = 0; n < 8; n++)
                    mma_f16(acc[i][n], ah[i], bh[n]);
        }
    }
    #undef PREFETCH

    int gid = lane >> 2, tig = lane & 3;
    if (mode == 0) {
        __half* Hc = (z == 0) ? H0 : ((z == 1) ? H1 : H2);
        #pragma unroll
        for (int i = 0; i < 2; i++) {
            int r = m0 + wm * 32 + i * 16 + gid;
            #pragma unroll
            for (int n = 0; n < 8; n++) {
                int col = n0 + wn * 64 + n * 8 + tig * 2;
                *(uint32_t*)(Hc + (size_t)r * DD + col) = pack_f16(acc[i][n][0], acc[i][n][1]);
                *(uint32_t*)(Hc + (size_t)(r + 8) * DD + col) = pack_f16(acc[i][n][2], acc[i][n][3]);
            }
        }
    } else {
        float sc = *scale_ptr;
        #pragma unroll
        for (int i = 0; i < 2; i++) {
            int r = m0 + wm * 32 + i * 16 + gid;
            #pragma unroll
            for (int n = 0; n < 8; n++) {
                int col = n0 + wn * 64 + n * 8 + tig * 2;
                float2 v0; v0.x = acc[i][n][0] * sc; v0.y = acc[i][n][1] * sc;
                float2 v1; v1.x = acc[i][n][2] * sc; v1.y = acc[i][n][3] * sc;
                *(float2*)(Cf + (size_t)r * DD + col) = v0;
                *(float2*)(Cf + (size_t)(r + 8) * DD + col) = v1;
            }
        }
    }
}

// ------------------------- MMA windowed decayed attention --------------------
// 64 q/CTA, NCH=4 chunks of 64 keys (window 256). Clamped rows + weight mask.
// 4-stage, single barrier per iteration (wait -> barrier -> prefetch -> compute).
#define NCH 4
#define SPITCH 528
#define SHI_OFF 0
#define PIPE_OFF 33792              // 64*528
#define APITCH 144
#define AOP    9216
#define ASTG   (2*AOP)              // 18432
#define VPITCH 272
#define VSTG   17408
#define ATT_SMEM (PIPE_OFF + 4*ASTG)   // 107520; x2 CTAs = 215040

__global__ __launch_bounds__(256, 2) void attn_mma(const float* __restrict__ decay_logit_p)
{
    extern __shared__ char smc[];
    uint32_t sb = smem_to_u32(smc);
    int t = threadIdx.x, lane = t & 31, w = t >> 5;
    int wq = w & 3, wn = w >> 2;
    int b = blockIdx.y, i0 = blockIdx.x * 64;

    float dl = *decay_logit_p;
    float decay = 1.0f / (1.0f + expf(-dl));
    float log2d = log2f(decay);
    const float qk_scale = 0.03125f;

    const __half* qh_g = g_qhi + (size_t)(b * TT + i0) * DD;
    const __half* kh_g = g_khi + (size_t)(b * TT) * DD;
    const __half* vh_g = g_vhi + (size_t)(b * TT) * DD;

    int mid = lane >> 3;
    int rl0 = wq * 16 + (lane >> 2);

    // ================= Phase A: scores =================
    const int totA = NCH * 16;

    #define PF_A(it) do { \
        int c_ = (it) >> 4, ds_ = (it) & 15; \
        int cs_ = i0 + c_ * 64; \
        uint32_t base_ = sb + PIPE_OFF + ((it) & 3) * ASTG; \
        _Pragma("unroll") \
        for (int i_ = 0; i_ < 2; i_++) { \
            int idx_ = t + 256 * i_; \
            int r_ = idx_ >> 3, g_ = idx_ & 7; \
            int krow_ = min(cs_ + r_, TT - 1); \
            uint32_t so_ = (uint32_t)(r_ * APITCH + g_ * 16); \
            size_t qo_ = (size_t)r_ * DD + ds_ * 64 + g_ * 8; \
            size_t ko_ = (size_t)krow_ * DD + ds_ * 64 + g_ * 8; \
            cp_async16(base_ + 0 * AOP + so_, qh_g + qo_); \
            cp_async16(base_ + 1 * AOP + so_, kh_g + ko_); \
        } \
    } while (0)

    {
        float acc[4][4];
        #pragma unroll
        for (int n = 0; n < 4; n++)
            #pragma unroll
            for (int j = 0; j < 4; j++) acc[n][j] = 0.f;

        PF_A(0); CP_COMMIT();
        PF_A(1); CP_COMMIT();
        PF_A(2); CP_COMMIT();

        for (int it = 0; it < totA; it++) {
            if (it <= totA - 3)      { CP_WAIT2(); }
            else if (it == totA - 2) { CP_WAIT1(); }
            else                     { CP_WAIT0(); }
            __syncthreads();
            if (it + 3 < totA) { PF_A(it + 3); CP_COMMIT(); }

            uint32_t base = sb + PIPE_OFF + (it & 3) * ASTG;
            #pragma unroll
            for (int kk = 0; kk < 4; kk++) {
                uint32_t qh[4];
                uint32_t roA = (uint32_t)((wq * 16 + (lane & 15)) * APITCH
                                          + kk * 32 + (lane >> 4) * 16);
                ldsm_x4(qh, base + 0 * AOP + roA);
                uint32_t kh[4][2];
                #pragma unroll
                for (int p = 0; p < 2; p++) {
                    int nr = wn * 32 + p * 16 + ((mid & 2) << 2) + (lane & 7);
                    uint32_t roB = (uint32_t)(nr * APITCH + kk * 32 + (mid & 1) * 16);
                    uint32_t r4[4];
                    ldsm_x4(r4, base + 1 * AOP + roB);
                    kh[2*p][0] = r4[0]; kh[2*p][1] = r4[1];
                    kh[2*p+1][0] = r4[2]; kh[2*p+1][1] = r4[3];
                }
                #pragma unroll
                for (int n = 0; n < 4; n++)
                    mma_f16(acc[n], qh, kh[n]);
            }

            if ((it & 15) == 15) {
                int c = it >> 4;
                #pragma unroll
                for (int n = 0; n < 4; n++) {
                    int jl0 = wn * 32 + n * 8 + (lane & 3) * 2;
                    float s[4];
                    #pragma unroll
                    for (int rr = 0; rr < 2; rr++) {
                        int rl = rl0 + rr * 8;
                        #pragma unroll
                        for (int jj = 0; jj < 2; jj++) {
                            int jg = i0 + c * 64 + jl0 + jj;
                            int iq = i0 + rl;
                            float wt = 0.f;
                            if (jg > iq && jg < TT)
                                wt = qk_scale * exp2f((float)(jg - iq - 1) * log2d);
                            s[rr * 2 + jj] = acc[n][rr * 2 + jj] * wt;
                        }
                    }
                    uint32_t jbyte = (uint32_t)((c * 64 + jl0) * 2);
                    #pragma unroll
                    for (int rr = 0; rr < 2; rr++) {
                        int rl = rl0 + rr * 8;
                        uint32_t ad = (uint32_t)(rl * SPITCH) + jbyte;
                        *(uint32_t*)(smc + SHI_OFF + ad) = pack_f16(s[rr*2], s[rr*2+1]);
                    }
                    #pragma unroll
                    for (int j = 0; j < 4; j++) acc[n][j] = 0.f;
                }
            }
        }
    }
    #undef PF_A
    __syncthreads();

    // ================= Phase B: O = S V =================
    const int totB = 8 * NCH;

    #define PF_V(it) do { \
        int db_ = (it) >> 2, c_ = (it) & 3; \
        int cs_ = i0 + c_ * 64; \
        uint32_t base_ = sb + PIPE_OFF + ((it) & 3) * VSTG; \
        _Pragma("unroll") \
        for (int i_ = 0; i_ < 4; i_++) { \
            int idx_ = t + 256 * i_; \
            int r_ = idx_ >> 4, g_ = idx_ & 15; \
            int vrow_ = min(cs_ + r_, TT - 1); \
            uint32_t so_ = (uint32_t)(r_ * VPITCH + g_ * 16); \
            size_t go_ = (size_t)vrow_ * DD + db_ * 128 + g_ * 8; \
            cp_async16(base_ + so_, vh_g + go_); \
        } \
    } while (0)

    PF_V(0); CP_COMMIT();
    PF_V(1); CP_COMMIT();
    PF_V(2); CP_COMMIT();

    for (int db = 0; db < 8; db++) {
        float oacc[8][4];
        #pragma unroll
        for (int n = 0; n < 8; n++)
            #pragma unroll
            for (int j = 0; j < 4; j++) oacc[n][j] = 0.f;

        for (int c = 0; c < NCH; c++) {
            int it = db * NCH + c;
            if (it <= totB - 3)      { CP_WAIT2(); }
            else if (it == totB - 2) { CP_WAIT1(); }
            else                     { CP_WAIT0(); }
            __syncthreads();
            if (it + 3 < totB) { PF_V(it + 3); CP_COMMIT(); }

            uint32_t vb = sb + PIPE_OFF + (it & 3) * VSTG;
            #pragma unroll
            for (int ks = 0; ks < 4; ks++) {
                int kof = c * 64 + ks * 16;
                uint32_t sh4[4];
                uint32_t roA = (uint32_t)((wq * 16 + (lane & 15)) * SPITCH
                                          + (kof + (lane >> 4) * 8) * 2);
                ldsm_x4(sh4, sb + SHI_OFF + roA);
                uint32_t vh[8][2];
                #pragma unroll
                for (int p = 0; p < 4; p++) {
                    int dloc = wn * 64 + p * 16;
                    uint32_t roB = (uint32_t)((ks * 16 + (lane & 15)) * VPITCH
                                              + (dloc + (lane >> 4) * 8) * 2);
                    uint32_t r4[4];
                    ldsm_x4_t(r4, vb + roB);
                    vh[2*p][0] = r4[0]; vh[2*p][1] = r4[1];
                    vh[2*p+1][0] = r4[2]; vh[2*p+1][1] = r4[3];
                }
                #pragma unroll
                for (int n = 0; n < 8; n++)
                    mma_f16(oacc[n], sh4, vh[n]);
            }
        }

        #pragma unroll
        for (int n = 0; n < 8; n++) {
            int d = db * 128 + wn * 64 + n * 8 + (lane & 3) * 2;
            #pragma unroll
            for (int rr = 0; rr < 2; rr++) {
                int row = i0 + rl0 + rr * 8;
                size_t ad = (size_t)(b * TT + row) * DD + d;
                *(uint32_t*)(g_rhi + ad) = pack_f16(oacc[n][rr*2], oacc[n][rr*2+1]);
            }
        }
    }
    #undef PF_V
}

// ---------------------------------------------------------------------------
extern "C" void kernel_launch(void* const* d_in, const int* in_sizes, int n_in,
                              void* d_out, int out_size)
{
    const float* x  = (const float*)d_in[0];
    const float* Wq = (const float*)d_in[1];
    const float* Wk = (const float*)d_in[2];
    const float* Wv = (const float*)d_in[3];
    const float* Wo = (const float*)d_in[4];
    const float* decay_logit = (const float*)d_in[5];
    const float* out_scale   = (const float*)d_in[6];
    float* out = (float*)d_out;

    __half *xhi, *whi, *qhi, *khi, *vhi, *rhi;
    cudaGetSymbolAddress((void**)&xhi, g_xhi);
    cudaGetSymbolAddress((void**)&whi, g_whi);
    cudaGetSymbolAddress((void**)&qhi, g_qhi);
    cudaGetSymbolAddress((void**)&khi, g_khi);
    cudaGetSymbolAddress((void**)&vhi, g_vhi);
    cudaGetSymbolAddress((void**)&rhi, g_rhi);

    int nx4 = M_TOTAL * DD / 4;
    int nw4 = DD * DD / 4;
    conv_x<<<(nx4 + 255) / 256, 256>>>(x, xhi, nx4);
    conv_w4<<<dim3((nw4 + 255) / 256, 4), 256>>>(Wq, Wk, Wv, Wo, whi, nw4);

    cudaFuncSetAttribute(mma_gemm, cudaFuncAttributeMaxDynamicSharedMemorySize, GSMEM);
    cudaFuncSetAttribute(attn_mma, cudaFuncAttributeMaxDynamicSharedMemorySize, ATT_SMEM);

    // QKV projections (1-pass each)
    mma_gemm<<<dim3(M_TOTAL / 128, DD / 128, 3), 256, GSMEM>>>(
        xhi, whi, qhi, khi, vhi, nullptr, nullptr, 0);

    // windowed decayed attention
    attn_mma<<<dim3(TT / 64, BB), 256, ATT_SMEM>>>(decay_logit);

    // output projection (fp32 out, scaled)
    mma_gemm<<<dim3(M_TOTAL / 128, DD / 128, 1), 256, GSMEM>>>(
        rhi, whi + 3 * (size_t)DD * DD, nullptr, nullptr, nullptr,
        out, out_scale, 1);
}

// round 15
// speedup vs baseline: 1.1029x; 1.1029x over previous
#include <cuda_runtime.h>
#include <cuda_fp16.h>
#include <math.h>
#include <stdint.h>

#define BB 4
#define TT 4096
#define DD 1024
#define M_TOTAL (BB*TT)

// ------------------------- scratch (device globals) -------------------------
__device__ __half g_xhi[M_TOTAL*DD];
__device__ __half g_whi[4*DD*DD];
__device__ __half g_qhi[M_TOTAL*DD];
__device__ __half g_khi[M_TOTAL*DD];
__device__ __half g_vhi[M_TOTAL*DD];
__device__ __half g_rhi[M_TOTAL*DD];

// ------------------------- helpers ------------------------------------------
__device__ __forceinline__ uint32_t smem_to_u32(const void* p) {
    uint32_t a;
    asm("{ .reg .u64 t; cvta.to.shared.u64 t, %1; cvt.u32.u64 %0, t; }" : "=r"(a) : "l"(p));
    return a;
}
__device__ __forceinline__ void cp_async16(uint32_t saddr, const void* g) {
    asm volatile("cp.async.cg.shared.global [%0], [%1], 16;" :: "r"(saddr), "l"(g));
}
#define CP_COMMIT() asm volatile("cp.async.commit_group;" ::: "memory")
#define CP_WAIT2()  asm volatile("cp.async.wait_group 2;" ::: "memory")
#define CP_WAIT1()  asm volatile("cp.async.wait_group 1;" ::: "memory")
#define CP_WAIT0()  asm volatile("cp.async.wait_group 0;" ::: "memory")

__device__ __forceinline__ void ldsm_x4(uint32_t* r, uint32_t addr) {
    asm volatile("ldmatrix.sync.aligned.m8n8.x4.shared.b16 {%0,%1,%2,%3}, [%4];"
        : "=r"(r[0]), "=r"(r[1]), "=r"(r[2]), "=r"(r[3]) : "r"(addr));
}
__device__ __forceinline__ void ldsm_x4_t(uint32_t* r, uint32_t addr) {
    asm volatile("ldmatrix.sync.aligned.m8n8.x4.trans.shared.b16 {%0,%1,%2,%3}, [%4];"
        : "=r"(r[0]), "=r"(r[1]), "=r"(r[2]), "=r"(r[3]) : "r"(addr));
}
__device__ __forceinline__ void mma_f16(float* d, const uint32_t* a, const uint32_t* b) {
    asm volatile("mma.sync.aligned.m16n8k16.row.col.f32.f16.f16.f32 "
        "{%0,%1,%2,%3}, {%4,%5,%6,%7}, {%8,%9}, {%0,%1,%2,%3};"
        : "+f"(d[0]), "+f"(d[1]), "+f"(d[2]), "+f"(d[3])
        : "r"(a[0]), "r"(a[1]), "r"(a[2]), "r"(a[3]), "r"(b[0]), "r"(b[1]));
}
__device__ __forceinline__ uint32_t pack_f16(float a, float b) {
    __half2 h = __floats2half2_rn(a, b);
    return *(uint32_t*)&h;
}

// ------------------------- conversion kernels --------------------------------
__global__ __launch_bounds__(256) void conv_x(
    const float* __restrict__ src, __half* __restrict__ hi, int n4)
{
    int i = blockIdx.x * 256 + threadIdx.x;
    if (i >= n4) return;
    float4 v = ((const float4*)src)[i];
    __half2 H0; H0.x = __float2half_rn(v.x); H0.y = __float2half_rn(v.y);
    __half2 H1; H1.x = __float2half_rn(v.z); H1.y = __float2half_rn(v.w);
    ((__half2*)hi)[2*i]   = H0;
    ((__half2*)hi)[2*i+1] = H1;
}

__global__ __launch_bounds__(256) void conv_w4(
    const float* __restrict__ s0, const float* __restrict__ s1,
    const float* __restrict__ s2, const float* __restrict__ s3,
    __half* __restrict__ hi, int n4)
{
    int i = blockIdx.x * 256 + threadIdx.x;
    if (i >= n4) return;
    int z = blockIdx.y;
    const float* src = (z == 0) ? s0 : ((z == 1) ? s1 : ((z == 2) ? s2 : s3));
    __half* dst = hi + (size_t)z * DD * DD;
    float4 v = ((const float4*)src)[i];
    __half2 H0; H0.x = __float2half_rn(v.x); H0.y = __float2half_rn(v.y);
    __half2 H1; H1.x = __float2half_rn(v.z); H1.y = __float2half_rn(v.w);
    ((__half2*)dst)[2*i]   = H0;
    ((__half2*)dst)[2*i+1] = H1;
}

// ------------------------- HMMA GEMM (128x128, BK=32, 4-stage) ---------------
// Per-iter order: wait(stage c) -> barrier -> prefetch(c+3) -> compute(c).
#define AHI_O 0
#define BHI_O 10240
#define STAGEB 20480
#define GSMEM  (4*STAGEB)          // 81920; x2 CTAs = 163840

__global__ __launch_bounds__(256, 2) void mma_gemm(
    const __half* __restrict__ Ahi, const __half* __restrict__ Whi,
    __half* __restrict__ H0, __half* __restrict__ H1, __half* __restrict__ H2,
    float* __restrict__ Cf, const float* __restrict__ scale_ptr, int mode)
{
    extern __shared__ char smc[];
    uint32_t sb = smem_to_u32(smc);
    int t = threadIdx.x, lane = t & 31, w = t >> 5;
    int wm = w & 3, wn = w >> 2;
    int m0 = blockIdx.x * 128, n0 = blockIdx.y * 128, z = blockIdx.z;

    const __half* Wh = Whi + (size_t)z * DD * DD;
    const __half* aH = Ahi + (size_t)m0 * DD;
    const __half* bH = Wh + (size_t)n0 * DD;

    float acc[2][8][4];
    #pragma unroll
    for (int i = 0; i < 2; i++)
        #pragma unroll
        for (int n = 0; n < 8; n++)
            #pragma unroll
            for (int j = 0; j < 4; j++) acc[i][n][j] = 0.f;

    int lrA = t >> 1, lsA = t & 1;
    uint32_t soA = (uint32_t)(lrA * 80 + lsA * 32);
    size_t goA = (size_t)lrA * DD + lsA * 16;

    #define PREFETCH(c) do { \
        uint32_t base_ = sb + ((c) & 3) * STAGEB; \
        int k0_ = (c) * 32; \
        cp_async16(base_ + AHI_O + soA,      aH + goA + k0_); \
        cp_async16(base_ + AHI_O + soA + 16, aH + goA + k0_ + 8); \
        cp_async16(base_ + BHI_O + soA,      bH + goA + k0_); \
        cp_async16(base_ + BHI_O + soA + 16, bH + goA + k0_ + 8); \
    } while (0)

    PREFETCH(0); CP_COMMIT();
    PREFETCH(1); CP_COMMIT();
    PREFETCH(2); CP_COMMIT();

    for (int c = 0; c < 32; c++) {
        if (c <= 29)      { CP_WAIT2(); }
        else if (c == 30) { CP_WAIT1(); }
        else              { CP_WAIT0(); }
        __syncthreads();
        if (c + 3 < 32) { PREFETCH(c + 3); CP_COMMIT(); }

        uint32_t base = sb + (c & 3) * STAGEB;
        #pragma unroll
        for (int kk = 0; kk < 2; kk++) {
            uint32_t ah[2][4];
            #pragma unroll
            for (int i = 0; i < 2; i++) {
                uint32_t ro = (uint32_t)((wm * 32 + i * 16 + (lane & 15)) * 80
                                         + kk * 32 + (lane >> 4) * 16);
                ldsm_x4(ah[i], base + AHI_O + ro);
            }
            uint32_t bh[8][2];
            #pragma unroll
            for (int p = 0; p < 4; p++) {
                int mid = lane >> 3;
                int nr = wn * 64 + p * 16 + ((mid & 2) << 2) + (lane & 7);
                uint32_t ro = (uint32_t)(nr * 80 + kk * 32 + (mid & 1) * 16);
                uint32_t r4[4];
                ldsm_x4(r4, base + BHI_O + ro);
                bh[2*p][0] = r4[0]; bh[2*p][1] = r4[1];
                bh[2*p+1][0] = r4[2]; bh[2*p+1][1] = r4[3];
            }
            #pragma unroll
            for (int i = 0; i < 2; i++)
                #pragma unroll
                for (int n = 0; n < 8; n++)
                    mma_f16(acc[i][n], ah[i], bh[n]);
        }
    }
    #undef PREFETCH

    int gid = lane >> 2, tig = lane & 3;
    if (mode == 0) {
        __half* Hc = (z == 0) ? H0 : ((z == 1) ? H1 : H2);
        #pragma unroll
        for (int i = 0; i < 2; i++) {
            int r = m0 + wm * 32 + i * 16 + gid;
            #pragma unroll
            for (int n = 0; n < 8; n++) {
                int col = n0 + wn * 64 + n * 8 + tig * 2;
                *(uint32_t*)(Hc + (size_t)r * DD + col) = pack_f16(acc[i][n][0], acc[i][n][1]);
                *(uint32_t*)(Hc + (size_t)(r + 8) * DD + col) = pack_f16(acc[i][n][2], acc[i][n][3]);
            }
        }
    } else {
        float sc = *scale_ptr;
        #pragma unroll
        for (int i = 0; i < 2; i++) {
            int r = m0 + wm * 32 + i * 16 + gid;
            #pragma unroll
            for (int n = 0; n < 8; n++) {
                int col = n0 + wn * 64 + n * 8 + tig * 2;
                float2 v0; v0.x = acc[i][n][0] * sc; v0.y = acc[i][n][1] * sc;
                float2 v1; v1.x = acc[i][n][2] * sc; v1.y = acc[i][n][3] * sc;
                *(float2*)(Cf + (size_t)r * DD + col) = v0;
                *(float2*)(Cf + (size_t)(r + 8) * DD + col) = v1;
            }
        }
    }
}

// ------------------------- MMA windowed decayed attention --------------------
// 64 q/CTA, NCH=4 chunks of 64 keys (window 256). Clamped rows + weight mask.
// 4-stage, single barrier per iteration (wait -> barrier -> prefetch -> compute).
#define NCH 4
#define SPITCH 528
#define SHI_OFF 0
#define PIPE_OFF 33792              // 64*528
#define APITCH 144
#define AOP    9216
#define ASTG   (2*AOP)              // 18432
#define VPITCH 272
#define VSTG   17408
#define ATT_SMEM (PIPE_OFF + 4*ASTG)   // 107520; x2 CTAs = 215040

__global__ __launch_bounds__(256, 2) void attn_mma(const float* __restrict__ decay_logit_p)
{
    extern __shared__ char smc[];
    uint32_t sb = smem_to_u32(smc);
    int t = threadIdx.x, lane = t & 31, w = t >> 5;
    int wq = w & 3, wn = w >> 2;
    int b = blockIdx.y, i0 = blockIdx.x * 64;

    float dl = *decay_logit_p;
    float decay = 1.0f / (1.0f + expf(-dl));
    float log2d = log2f(decay);
    const float qk_scale = 0.03125f;

    const __half* qh_g = g_qhi + (size_t)(b * TT + i0) * DD;
    const __half* kh_g = g_khi + (size_t)(b * TT) * DD;
    const __half* vh_g = g_vhi + (size_t)(b * TT) * DD;

    int mid = lane >> 3;
    int rl0 = wq * 16 + (lane >> 2);

    // ================= Phase A: scores =================
    const int totA = NCH * 16;

    #define PF_A(it) do { \
        int c_ = (it) >> 4, ds_ = (it) & 15; \
        int cs_ = i0 + c_ * 64; \
        uint32_t base_ = sb + PIPE_OFF + ((it) & 3) * ASTG; \
        _Pragma("unroll") \
        for (int i_ = 0; i_ < 2; i_++) { \
            int idx_ = t + 256 * i_; \
            int r_ = idx_ >> 3, g_ = idx_ & 7; \
            int krow_ = min(cs_ + r_, TT - 1); \
            uint32_t so_ = (uint32_t)(r_ * APITCH + g_ * 16); \
            size_t qo_ = (size_t)r_ * DD + ds_ * 64 + g_ * 8; \
            size_t ko_ = (size_t)krow_ * DD + ds_ * 64 + g_ * 8; \
            cp_async16(base_ + 0 * AOP + so_, qh_g + qo_); \
            cp_async16(base_ + 1 * AOP + so_, kh_g + ko_); \
        } \
    } while (0)

    {
        float acc[4][4];
        #pragma unroll
        for (int n = 0; n < 4; n++)
            #pragma unroll
            for (int j = 0; j < 4; j++) acc[n][j] = 0.f;

        PF_A(0); CP_COMMIT();
        PF_A(1); CP_COMMIT();
        PF_A(2); CP_COMMIT();

        for (int it = 0; it < totA; it++) {
            if (it <= totA - 3)      { CP_WAIT2(); }
            else if (it == totA - 2) { CP_WAIT1(); }
            else                     { CP_WAIT0(); }
            __syncthreads();
            if (it + 3 < totA) { PF_A(it + 3); CP_COMMIT(); }

            uint32_t base = sb + PIPE_OFF + (it & 3) * ASTG;
            #pragma unroll
            for (int kk = 0; kk < 4; kk++) {
                uint32_t qh[4];
                uint32_t roA = (uint32_t)((wq * 16 + (lane & 15)) * APITCH
                                          + kk * 32 + (lane >> 4) * 16);
                ldsm_x4(qh, base + 0 * AOP + roA);
                uint32_t kh[4][2];
                #pragma unroll
                for (int p = 0; p < 2; p++) {
                    int nr = wn * 32 + p * 16 + ((mid & 2) << 2) + (lane & 7);
                    uint32_t roB = (uint32_t)(nr * APITCH + kk * 32 + (mid & 1) * 16);
                    uint32_t r4[4];
                    ldsm_x4(r4, base + 1 * AOP + roB);
                    kh[2*p][0] = r4[0]; kh[2*p][1] = r4[1];
                    kh[2*p+1][0] = r4[2]; kh[2*p+1][1] = r4[3];
                }
                #pragma unroll
                for (int n = 0; n < 4; n++)
                    mma_f16(acc[n], qh, kh[n]);
            }

            if ((it & 15) == 15) {
                int c = it >> 4;
                #pragma unroll
                for (int n = 0; n < 4; n++) {
                    int jl0 = wn * 32 + n * 8 + (lane & 3) * 2;
                    float s[4];
                    #pragma unroll
                    for (int rr = 0; rr < 2; rr++) {
                        int rl = rl0 + rr * 8;
                        #pragma unroll
                        for (int jj = 0; jj < 2; jj++) {
                            int jg = i0 + c * 64 + jl0 + jj;
                            int iq = i0 + rl;
                            float wt = 0.f;
                            if (jg > iq && jg < TT)
                                wt = qk_scale * exp2f((float)(jg - iq - 1) * log2d);
                            s[rr * 2 + jj] = acc[n][rr * 2 + jj] * wt;
                        }
                    }
                    uint32_t jbyte = (uint32_t)((c * 64 + jl0) * 2);
                    #pragma unroll
                    for (int rr = 0; rr < 2; rr++) {
                        int rl = rl0 + rr * 8;
                        uint32_t ad = (uint32_t)(rl * SPITCH) + jbyte;
                        *(uint32_t*)(smc + SHI_OFF + ad) = pack_f16(s[rr*2], s[rr*2+1]);
                    }
                    #pragma unroll
                    for (int j = 0; j < 4; j++) acc[n][j] = 0.f;
                }
            }
        }
    }
    #undef PF_A
    __syncthreads();

    // ================= Phase B: O = S V =================
    const int totB = 8 * NCH;

    #define PF_V(it) do { \
        int db_ = (it) >> 2, c_ = (it) & 3; \
        int cs_ = i0 + c_ * 64; \
        uint32_t base_ = sb + PIPE_OFF + ((it) & 3) * VSTG; \
        _Pragma("unroll") \
        for (int i_ = 0; i_ < 4; i_++) { \
            int idx_ = t + 256 * i_; \
            int r_ = idx_ >> 4, g_ = idx_ & 15; \
            int vrow_ = min(cs_ + r_, TT - 1); \
            uint32_t so_ = (uint32_t)(r_ * VPITCH + g_ * 16); \
            size_t go_ = (size_t)vrow_ * DD + db_ * 128 + g_ * 8; \
            cp_async16(base_ + so_, vh_g + go_); \
        } \
    } while (0)

    PF_V(0); CP_COMMIT();
    PF_V(1); CP_COMMIT();
    PF_V(2); CP_COMMIT();

    for (int db = 0; db < 8; db++) {
        float oacc[8][4];
        #pragma unroll
        for (int n = 0; n < 8; n++)
            #pragma unroll
            for (int j = 0; j < 4; j++) oacc[n][j] = 0.f;

        for (int c = 0; c < NCH; c++) {
            int it = db * NCH + c;
            if (it <= totB - 3)      { CP_WAIT2(); }
            else if (it == totB - 2) { CP_WAIT1(); }
            else                     { CP_WAIT0(); }
            __syncthreads();
            if (it + 3 < totB) { PF_V(it + 3); CP_COMMIT(); }

            uint32_t vb = sb + PIPE_OFF + (it & 3) * VSTG;
            #pragma unroll
            for (int ks = 0; ks < 4; ks++) {
                int kof = c * 64 + ks * 16;
                uint32_t sh4[4];
                uint32_t roA = (uint32_t)((wq * 16 + (lane & 15)) * SPITCH
                                          + (kof + (lane >> 4) * 8) * 2);
                ldsm_x4(sh4, sb + SHI_OFF + roA);
                uint32_t vh[8][2];
                #pragma unroll
                for (int p = 0; p < 4; p++) {
                    int dloc = wn * 64 + p * 16;
                    uint32_t roB = (uint32_t)((ks * 16 + (lane & 15)) * VPITCH
                                              + (dloc + (lane >> 4) * 8) * 2);
                    uint32_t r4[4];
                    ldsm_x4_t(r4, vb + roB);
                    vh[2*p][0] = r4[0]; vh[2*p][1] = r4[1];
                    vh[2*p+1][0] = r4[2]; vh[2*p+1][1] = r4[3];
                }
                #pragma unroll
                for (int n = 0; n < 8; n++)
                    mma_f16(oacc[n], sh4, vh[n]);
            }
        }

        #pragma unroll
        for (int n = 0; n < 8; n++) {
            int d = db * 128 + wn * 64 + n * 8 + (lane & 3) * 2;
            #pragma unroll
            for (int rr = 0; rr < 2; rr++) {
                int row = i0 + rl0 + rr * 8;
                size_t ad = (size_t)(b * TT + row) * DD + d;
                *(uint32_t*)(g_rhi + ad) = pack_f16(oacc[n][rr*2], oacc[n][rr*2+1]);
            }
        }
    }
    #undef PF_V
}

// ---------------------------------------------------------------------------
extern "C" void kernel_launch(void* const* d_in, const int* in_sizes, int n_in,
                              void* d_out, int out_size)
{
    const float* x  = (const float*)d_in[0];
    const float* Wq = (const float*)d_in[1];
    const float* Wk = (const float*)d_in[2];
    const float* Wv = (const float*)d_in[3];
    const float* Wo = (const float*)d_in[4];
    const float* decay_logit = (const float*)d_in[5];
    const float* out_scale   = (const float*)d_in[6];
    float* out = (float*)d_out;

    __half *xhi, *whi, *qhi, *khi, *vhi, *rhi;
    cudaGetSymbolAddress((void**)&xhi, g_xhi);
    cudaGetSymbolAddress((void**)&whi, g_whi);
    cudaGetSymbolAddress((void**)&qhi, g_qhi);
    cudaGetSymbolAddress((void**)&khi, g_khi);
    cudaGetSymbolAddress((void**)&vhi, g_vhi);
    cudaGetSymbolAddress((void**)&rhi, g_rhi);

    int nx4 = M_TOTAL * DD / 4;
    int nw4 = DD * DD / 4;
    conv_x<<<(nx4 + 255) / 256, 256>>>(x, xhi, nx4);
    conv_w4<<<dim3((nw4 + 255) / 256, 4), 256>>>(Wq, Wk, Wv, Wo, whi, nw4);

    cudaFuncSetAttribute(mma_gemm, cudaFuncAttributeMaxDynamicSharedMemorySize, GSMEM);
    cudaFuncSetAttribute(attn_mma, cudaFuncAttributeMaxDynamicSharedMemorySize, ATT_SMEM);

    // QKV projections (1-pass each)
    mma_gemm<<<dim3(M_TOTAL / 128, DD / 128, 3), 256, GSMEM>>>(
        xhi, whi, qhi, khi, vhi, nullptr, nullptr, 0);

    // windowed decayed attention
    attn_mma<<<dim3(TT / 64, BB), 256, ATT_SMEM>>>(decay_logit);

    // output projection (fp32 out, scaled)
    mma_gemm<<<dim3(M_TOTAL / 128, DD / 128, 1), 256, GSMEM>>>(
        rhi, whi + 3 * (size_t)DD * DD, nullptr, nullptr, nullptr,
        out, out_scale, 1);
}